// round 14
// baseline (speedup 1.0000x reference)
#include <cuda_runtime.h>
#include <cuda_fp16.h>
#include <math.h>

#define N_NODES 100000
#define N_EDGES 1200000
#define COL_CAP (N_EDGES + 3 * N_NODES + 16)
#define HID 64
#define G_NUM 128
#define C_OUT 10
#define D_IN 3
#define EPS_BN 1e-5f

static __device__ __forceinline__ unsigned int h2_bits(__half2 h) {
    return *reinterpret_cast<unsigned int*>(&h);
}
static __device__ __forceinline__ __half2 bits_h2(unsigned int u) {
    return *reinterpret_cast<__half2*>(&u);
}

// -------- scratch (static device globals; no runtime allocation) --------
__device__ int   g_ecnt[N_NODES];
__device__ int   g_base[N_NODES];     // after k_base: aligned start; after fill: start+cnt
__device__ __align__(16) int g_col[COL_CAP];
__device__ int   g_tot;
__device__ __align__(16) __half g_xwh[N_NODES * HID];   // (h@W)*dinv, fp16
__device__ __align__(16) float  g_h  [N_NODES * HID];   // layer output, fp32

// grid barrier state (self-resetting across replays)
__device__ unsigned int g_bar_cnt = 0;
__device__ volatile unsigned int g_bar_gen = 0;

// -------- in-degree over real edges (4 edges/thread via int4) --------
__global__ void __launch_bounds__(256) k_deg(const int* __restrict__ ei) {
    int idx = blockIdx.x * blockDim.x + threadIdx.x;           // < E/4
    if (idx >= N_EDGES / 4) return;
    int4 d = ((const int4*)(ei + N_EDGES))[idx];
    atomicAdd(&g_ecnt[d.x], 1);
    atomicAdd(&g_ecnt[d.y], 1);
    atomicAdd(&g_ecnt[d.z], 1);
    atomicAdd(&g_ecnt[d.w], 1);
}

// -------- CSR bases, 4-aligned allocations (warp scan + atomic) --------
__global__ void k_base() {
    int i = blockIdx.x * blockDim.x + threadIdx.x;
    int lane = threadIdx.x & 31;
    int c = (i < N_NODES) ? g_ecnt[i] : 0;
    int alloc = (c + 3) & ~3;
    int incl = alloc;
    #pragma unroll
    for (int off = 1; off < 32; off <<= 1) {
        int v = __shfl_up_sync(0xffffffffu, incl, off);
        if (lane >= off) incl += v;
    }
    int excl = incl - alloc;
    int wsum = __shfl_sync(0xffffffffu, incl, 31);
    int wbase = 0;
    if (lane == 31) wbase = atomicAdd(&g_tot, wsum);
    wbase = __shfl_sync(0xffffffffu, wbase, 31);
    if (i < N_NODES) g_base[i] = wbase + excl;
}

// -------- merged: CSR fill + layer-0 linear ----------------------------------
#define NB_FILL ((N_EDGES / 2 + 255) / 256)
#define NB_L0   ((N_NODES * 16 + 255) / 256)
__global__ void __launch_bounds__(256) k_fill_lin0(const int* __restrict__ ei,
                                                   const float* __restrict__ x,
                                                   const float* __restrict__ W0) {
    if (blockIdx.x < NB_FILL) {
        int idx = blockIdx.x * blockDim.x + threadIdx.x;       // < E/2
        if (idx >= N_EDGES / 2) return;
        int2 s = ((const int2*)ei)[idx];
        int2 d = ((const int2*)(ei + N_EDGES))[idx];
        int p0 = atomicAdd(&g_base[d.x], 1); g_col[p0] = s.x;
        int p1 = atomicAdd(&g_base[d.y], 1); g_col[p1] = s.y;
    } else {
        __shared__ float sW[D_IN * HID];
        int t = threadIdx.x;
        if (t < D_IN * HID) sW[t] = W0[t];
        __syncthreads();
        int idx = (blockIdx.x - NB_FILL) * blockDim.x + t;     // < N*16
        if (idx >= N_NODES * 16) return;
        int i = idx >> 4, j4 = idx & 15;
        float x0 = x[i * 3 + 0], x1 = x[i * 3 + 1], x2 = x[i * 3 + 2];
        float d = rsqrtf((float)(g_ecnt[i] + 1));
        float o[4];
        #pragma unroll
        for (int q = 0; q < 4; q++) {
            int j = 4 * j4 + q;
            o[q] = (x0 * sW[j] + x1 * sW[64 + j] + x2 * sW[128 + j]) * d;
        }
        uint2 pk;
        pk.x = h2_bits(__floats2half2_rn(o[0], o[1]));
        pk.y = h2_bits(__floats2half2_rn(o[2], o[3]));
        ((uint2*)g_xwh)[idx] = pk;
    }
}

// ======================= fused persistent pipeline ===========================
// phases: gather0 | linh1 | gather1 | linh2 | gather2 | poolcls
// grid barrier between phases; grid sized to full residency by host.

static __device__ __forceinline__ void grid_barrier(int nblocks) {
    __syncthreads();
    if (threadIdx.x == 0) {
        unsigned int gen = g_bar_gen;
        __threadfence();
        unsigned int arrived = atomicAdd(&g_bar_cnt, 1u);
        if (arrived == (unsigned int)nblocks - 1u) {
            atomicExch(&g_bar_cnt, 0u);
            __threadfence();
            g_bar_gen = gen + 1u;
        } else {
            while (g_bar_gen == gen) __nanosleep(64);
            __threadfence();
        }
    }
    __syncthreads();
}

// gather one 16-node tile (256 threads, 16 thr/node, uint2 rows, 8 in flight)
static __device__ __forceinline__ void gather_tile(int tile,
        const float* __restrict__ bb, const float* __restrict__ gamma,
        const float* __restrict__ beta, const float* __restrict__ mean,
        const float* __restrict__ var, int relu) {
    int t = threadIdx.x;
    int node = tile * 16 + (t >> 4);
    int j4 = t & 15;
    const uint2* xw2 = (const uint2*)g_xwh;

    int cnt  = g_ecnt[node];
    int base = g_base[node] - cnt;

    uint2 self = xw2[node * 16 + j4];
    float2 slo = __half22float2(bits_h2(self.x));
    float2 shi = __half22float2(bits_h2(self.y));
    float4 acc = make_float4(slo.x, slo.y, shi.x, shi.y);

    const int4* c4p = (const int4*)(g_col + base);
    int k = 0;
    for (; k + 8 <= cnt; k += 8) {
        int4 ca = __ldg(&c4p[(k >> 2) + 0]);
        int4 cb = __ldg(&c4p[(k >> 2) + 1]);
        uint2 r0 = __ldg(&xw2[ca.x * 16 + j4]);
        uint2 r1 = __ldg(&xw2[ca.y * 16 + j4]);
        uint2 r2 = __ldg(&xw2[ca.z * 16 + j4]);
        uint2 r3 = __ldg(&xw2[ca.w * 16 + j4]);
        uint2 r4 = __ldg(&xw2[cb.x * 16 + j4]);
        uint2 r5 = __ldg(&xw2[cb.y * 16 + j4]);
        uint2 r6 = __ldg(&xw2[cb.z * 16 + j4]);
        uint2 r7 = __ldg(&xw2[cb.w * 16 + j4]);
        __half2 lo = __hadd2(__hadd2(__hadd2(bits_h2(r0.x), bits_h2(r1.x)),
                                     __hadd2(bits_h2(r2.x), bits_h2(r3.x))),
                             __hadd2(__hadd2(bits_h2(r4.x), bits_h2(r5.x)),
                                     __hadd2(bits_h2(r6.x), bits_h2(r7.x))));
        __half2 hi = __hadd2(__hadd2(__hadd2(bits_h2(r0.y), bits_h2(r1.y)),
                                     __hadd2(bits_h2(r2.y), bits_h2(r3.y))),
                             __hadd2(__hadd2(bits_h2(r4.y), bits_h2(r5.y)),
                                     __hadd2(bits_h2(r6.y), bits_h2(r7.y))));
        float2 flo = __half22float2(lo);
        float2 fhi = __half22float2(hi);
        acc.x += flo.x; acc.y += flo.y; acc.z += fhi.x; acc.w += fhi.y;
    }
    for (; k + 4 <= cnt; k += 4) {
        int4 c4 = __ldg(&c4p[k >> 2]);
        uint2 r0 = __ldg(&xw2[c4.x * 16 + j4]);
        uint2 r1 = __ldg(&xw2[c4.y * 16 + j4]);
        uint2 r2 = __ldg(&xw2[c4.z * 16 + j4]);
        uint2 r3 = __ldg(&xw2[c4.w * 16 + j4]);
        __half2 lo = __hadd2(__hadd2(bits_h2(r0.x), bits_h2(r1.x)),
                             __hadd2(bits_h2(r2.x), bits_h2(r3.x)));
        __half2 hi = __hadd2(__hadd2(bits_h2(r0.y), bits_h2(r1.y)),
                             __hadd2(bits_h2(r2.y), bits_h2(r3.y)));
        float2 flo = __half22float2(lo);
        float2 fhi = __half22float2(hi);
        acc.x += flo.x; acc.y += flo.y; acc.z += fhi.x; acc.w += fhi.y;
    }
    for (; k < cnt; k++) {
        int s = __ldg(&g_col[base + k]);
        uint2 r = __ldg(&xw2[s * 16 + j4]);
        float2 a = __half22float2(bits_h2(r.x));
        float2 b = __half22float2(bits_h2(r.y));
        acc.x += a.x; acc.y += a.y; acc.z += b.x; acc.w += b.y;
    }

    float d = rsqrtf((float)(cnt + 1));
    float4 vb  = ((const float4*)bb)[j4];
    float4 vg  = ((const float4*)gamma)[j4];
    float4 vbt = ((const float4*)beta)[j4];
    float4 vm  = ((const float4*)mean)[j4];
    float4 vv  = ((const float4*)var)[j4];
    float4 o;
    o.x = (acc.x * d + vb.x - vm.x) * (vg.x * rsqrtf(vv.x + EPS_BN)) + vbt.x;
    o.y = (acc.y * d + vb.y - vm.y) * (vg.y * rsqrtf(vv.y + EPS_BN)) + vbt.y;
    o.z = (acc.z * d + vb.z - vm.z) * (vg.z * rsqrtf(vv.z + EPS_BN)) + vbt.z;
    o.w = (acc.w * d + vb.w - vm.w) * (vg.w * rsqrtf(vv.w + EPS_BN)) + vbt.w;
    if (relu) {
        o.x = fmaxf(o.x, 0.f); o.y = fmaxf(o.y, 0.f);
        o.z = fmaxf(o.z, 0.f); o.w = fmaxf(o.w, 0.f);
    }
    ((float4*)g_h)[node * 16 + j4] = o;
}

// register-tiled 64x64 GEMM tile; sbuf >= 32KB
static __device__ __forceinline__ void linh_tile(int tile, const float* __restrict__ W,
                                                 char* sbuf) {
    float* sW  = (float*)sbuf;            // 16KB, k-major
    float* shT = (float*)(sbuf + 16384);  // 16KB, transposed
    int t = threadIdx.x;
    int node0 = tile * 64;

    for (int q = t; q < 1024; q += 256)
        ((float4*)sW)[q] = ((const float4*)W)[q];

    int ln = t & 63;
    int c0 = t >> 6;
    #pragma unroll
    for (int cc = c0; cc < 16; cc += 4) {
        int gi = node0 + ln;
        float4 v = make_float4(0.f, 0.f, 0.f, 0.f);
        if (gi < N_NODES) v = ((const float4*)g_h)[gi * 16 + cc];
        shT[(4 * cc + 0) * 64 + ln] = v.x;
        shT[(4 * cc + 1) * 64 + ln] = v.y;
        shT[(4 * cc + 2) * 64 + ln] = v.z;
        shT[(4 * cc + 3) * 64 + ln] = v.w;
    }
    __syncthreads();

    int a = t >> 4;
    int b = t & 15;
    float4 acc0 = make_float4(0.f, 0.f, 0.f, 0.f);
    float4 acc1 = acc0, acc2 = acc0, acc3 = acc0;

    #pragma unroll 8
    for (int k = 0; k < 64; k++) {
        float4 vN = *(const float4*)&shT[k * 64 + 4 * a];
        float4 vW = *(const float4*)&sW [k * 64 + 4 * b];
        acc0.x += vN.x * vW.x; acc0.y += vN.x * vW.y; acc0.z += vN.x * vW.z; acc0.w += vN.x * vW.w;
        acc1.x += vN.y * vW.x; acc1.y += vN.y * vW.y; acc1.z += vN.y * vW.z; acc1.w += vN.y * vW.w;
        acc2.x += vN.z * vW.x; acc2.y += vN.z * vW.y; acc2.z += vN.z * vW.z; acc2.w += vN.z * vW.w;
        acc3.x += vN.w * vW.x; acc3.y += vN.w * vW.y; acc3.z += vN.w * vW.z; acc3.w += vN.w * vW.w;
    }

    float4 accs[4] = {acc0, acc1, acc2, acc3};
    #pragma unroll
    for (int r = 0; r < 4; r++) {
        int i = node0 + 4 * a + r;
        if (i < N_NODES) {
            float d = rsqrtf((float)(g_ecnt[i] + 1));
            float4 o = accs[r];
            uint2 pk;
            pk.x = h2_bits(__floats2half2_rn(o.x * d, o.y * d));
            pk.y = h2_bits(__floats2half2_rn(o.z * d, o.w * d));
            ((uint2*)g_xwh)[i * 16 + b] = pk;
        }
    }
    __syncthreads();   // protect sbuf reuse across tile iterations
}

static __device__ __forceinline__ void poolcls_graph(int g, char* sbuf,
        const int* __restrict__ batch,
        const float* __restrict__ Wc1, const float* __restrict__ bc1,
        const float* __restrict__ Wc2, const float* __restrict__ bc2,
        float* __restrict__ out) {
    float* ssum = (float*)sbuf;                 // 16*65 floats
    float* smax = (float*)(sbuf + 4160);        // 16*65 floats
    float* gv   = (float*)(sbuf + 8320);        // 128
    float* hc   = (float*)(sbuf + 8832);        // 64
    float* lg   = (float*)(sbuf + 9088);        // 10
    float* lse  = (float*)(sbuf + 9128);        // 1
    int*   sse  = (int*)  (sbuf + 9132);        // 2

    int t = threadIdx.x;
    if (t == 0) {
        int lo = 0, hi = N_NODES;
        while (lo < hi) { int m = (lo + hi) >> 1; if (batch[m] < g) lo = m + 1; else hi = m; }
        sse[0] = lo;
        lo = 0; hi = N_NODES;
        while (lo < hi) { int m = (lo + hi) >> 1; if (batch[m] < g + 1) lo = m + 1; else hi = m; }
        sse[1] = lo;
    }
    __syncthreads();
    int start = sse[0], end = sse[1];

    int r  = t >> 4;
    int j4 = t & 15;
    const float4* h4 = (const float4*)g_h;
    float4 sum = make_float4(0.f, 0.f, 0.f, 0.f);
    float4 mx  = make_float4(-INFINITY, -INFINITY, -INFINITY, -INFINITY);
    for (int i = start + r; i < end; i += 16) {
        float4 v = h4[i * 16 + j4];
        sum.x += v.x; sum.y += v.y; sum.z += v.z; sum.w += v.w;
        mx.x = fmaxf(mx.x, v.x); mx.y = fmaxf(mx.y, v.y);
        mx.z = fmaxf(mx.z, v.z); mx.w = fmaxf(mx.w, v.w);
    }
    ssum[r * 65 + 4 * j4 + 0] = sum.x; ssum[r * 65 + 4 * j4 + 1] = sum.y;
    ssum[r * 65 + 4 * j4 + 2] = sum.z; ssum[r * 65 + 4 * j4 + 3] = sum.w;
    smax[r * 65 + 4 * j4 + 0] = mx.x;  smax[r * 65 + 4 * j4 + 1] = mx.y;
    smax[r * 65 + 4 * j4 + 2] = mx.z;  smax[r * 65 + 4 * j4 + 3] = mx.w;
    __syncthreads();

    if (t < HID) {
        float s = 0.f, m = -INFINITY;
        #pragma unroll
        for (int q = 0; q < 16; q++) {
            s += ssum[q * 65 + t];
            m = fmaxf(m, smax[q * 65 + t]);
        }
        gv[t]       = s / (float)(end - start);
        gv[HID + t] = m;
    }
    __syncthreads();

    if (t < HID) {
        float s = bc1[t];
        #pragma unroll 16
        for (int k = 0; k < 2 * HID; k++) s += gv[k] * Wc1[k * HID + t];
        hc[t] = fmaxf(s, 0.f);
    }
    __syncthreads();

    if (t < C_OUT) {
        float l = bc2[t];
        #pragma unroll 16
        for (int j = 0; j < HID; j++) l += hc[j] * Wc2[j * C_OUT + t];
        lg[t] = l;
    }
    __syncthreads();

    if (t == 0) {
        float m = -INFINITY;
        #pragma unroll
        for (int c = 0; c < C_OUT; c++) m = fmaxf(m, lg[c]);
        float se = 0.f;
        #pragma unroll
        for (int c = 0; c < C_OUT; c++) se += expf(lg[c] - m);
        lse[0] = m + logf(se);
    }
    __syncthreads();
    if (t < C_OUT) out[g * C_OUT + t] = lg[t] - lse[0];
    __syncthreads();
}

__global__ void __launch_bounds__(256, 6) k_fused(
        const int* __restrict__ batch,
        const float* __restrict__ Ws, const float* __restrict__ bs,
        const float* __restrict__ gamma, const float* __restrict__ beta,
        const float* __restrict__ rmean, const float* __restrict__ rvar,
        const float* __restrict__ Wc1, const float* __restrict__ bc1,
        const float* __restrict__ Wc2, const float* __restrict__ bc2,
        float* __restrict__ out, int nblocks) {
    __shared__ __align__(16) char sbuf[32768];
    const int GT = N_NODES / 16;              // 6250 gather tiles
    const int LT = (N_NODES + 63) / 64;       // 1563 gemm tiles

    // gather layer 0
    for (int tile = blockIdx.x; tile < GT; tile += nblocks)
        gather_tile(tile, bs, gamma, beta, rmean, rvar, 1);
    grid_barrier(nblocks);
    // linear layer 1
    for (int tile = blockIdx.x; tile < LT; tile += nblocks)
        linh_tile(tile, Ws, sbuf);
    grid_barrier(nblocks);
    // gather layer 1
    for (int tile = blockIdx.x; tile < GT; tile += nblocks)
        gather_tile(tile, bs + HID, gamma + HID, beta + HID, rmean + HID, rvar + HID, 1);
    grid_barrier(nblocks);
    // linear layer 2
    for (int tile = blockIdx.x; tile < LT; tile += nblocks)
        linh_tile(tile, Ws + HID * HID, sbuf);
    grid_barrier(nblocks);
    // gather layer 2 (no relu)
    for (int tile = blockIdx.x; tile < GT; tile += nblocks)
        gather_tile(tile, bs + 2 * HID, gamma + 2 * HID, beta + 2 * HID,
                    rmean + 2 * HID, rvar + 2 * HID, 0);
    grid_barrier(nblocks);
    // pooling + classifier
    for (int g = blockIdx.x; g < G_NUM; g += nblocks)
        poolcls_graph(g, sbuf, batch, Wc1, bc1, Wc2, bc2, out);
}

extern "C" void kernel_launch(void* const* d_in, const int* in_sizes, int n_in,
                              void* d_out, int out_size) {
    const float* x     = (const float*)d_in[0];
    const int*   ei    = (const int*)  d_in[1];
    const int*   batch = (const int*)  d_in[2];
    // d_in[3] = num_graphs (constant 128, unused)
    const float* W0    = (const float*)d_in[4];
    const float* Ws    = (const float*)d_in[5];
    const float* bs    = (const float*)d_in[6];
    const float* gamma = (const float*)d_in[7];
    const float* beta  = (const float*)d_in[8];
    const float* rmean = (const float*)d_in[9];
    const float* rvar  = (const float*)d_in[10];
    const float* Wc1   = (const float*)d_in[11];
    const float* bc1   = (const float*)d_in[12];
    const float* Wc2   = (const float*)d_in[13];
    const float* bc2   = (const float*)d_in[14];
    float* out = (float*)d_out;

    const int NB_N  = (N_NODES + 255) / 256;
    const int NB_E4 = (N_EDGES / 4 + 255) / 256;

    // fully-resident grid for the persistent kernel (capture-safe queries)
    int dev = 0, nsm = 0, bpm = 0;
    cudaGetDevice(&dev);
    cudaDeviceGetAttribute(&nsm, cudaDevAttrMultiProcessorCount, dev);
    cudaOccupancyMaxActiveBlocksPerMultiprocessor(&bpm, k_fused, 256, 0);
    if (bpm < 1) bpm = 1;
    int nblocks = nsm * bpm;

    // zero-init counters via graph memset nodes
    void* p_ecnt = 0; void* p_tot = 0;
    cudaGetSymbolAddress(&p_ecnt, g_ecnt);
    cudaGetSymbolAddress(&p_tot,  g_tot);
    cudaMemsetAsync(p_ecnt, 0, N_NODES * sizeof(int));
    cudaMemsetAsync(p_tot,  0, sizeof(int));

    // CSR build (fill overlapped with layer-0 linear)
    k_deg      <<<NB_E4, 256>>>(ei);
    k_base     <<<NB_N, 256>>>();
    k_fill_lin0<<<NB_FILL + NB_L0, 256>>>(ei, x, W0);

    // fused persistent pipeline: 3 gathers + 2 linears + pool/classifier
    k_fused<<<nblocks, 256>>>(batch, Ws, bs, gamma, beta, rmean, rvar,
                              Wc1, bc1, Wc2, bc2, out, nblocks);
}

// round 15
// speedup vs baseline: 1.1120x; 1.1120x over previous
#include <cuda_runtime.h>
#include <cuda_fp16.h>
#include <math.h>

#define N_NODES 100000
#define N_EDGES 1200000
#define COL_CAP (N_EDGES + 3 * N_NODES + 16)
#define HID 64
#define G_NUM 128
#define C_OUT 10
#define D_IN 3
#define EPS_BN 1e-5f

static __device__ __forceinline__ unsigned int h2_bits(__half2 h) {
    return *reinterpret_cast<unsigned int*>(&h);
}
static __device__ __forceinline__ __half2 bits_h2(unsigned int u) {
    return *reinterpret_cast<__half2*>(&u);
}

// -------- scratch (static device globals; no runtime allocation) --------
__device__ int   g_ecnt[N_NODES];
__device__ int   g_base[N_NODES];     // after k_base: aligned start; after fill: start+cnt
__device__ __align__(16) int g_col[COL_CAP];
__device__ int   g_tot;
__device__ __align__(16) __half g_xwh[N_NODES * HID];   // (h@W)*dinv, fp16
__device__ __align__(16) float  g_h  [N_NODES * HID];   // layer output, fp32

// -------- in-degree over real edges (4 edges/thread via int4) --------
__global__ void __launch_bounds__(256) k_deg(const int* __restrict__ ei) {
    int idx = blockIdx.x * blockDim.x + threadIdx.x;           // < E/4
    if (idx >= N_EDGES / 4) return;
    int4 d = ((const int4*)(ei + N_EDGES))[idx];
    atomicAdd(&g_ecnt[d.x], 1);
    atomicAdd(&g_ecnt[d.y], 1);
    atomicAdd(&g_ecnt[d.z], 1);
    atomicAdd(&g_ecnt[d.w], 1);
}

// -------- CSR bases, 4-aligned allocations (warp scan + atomic) --------
__global__ void k_base() {
    int i = blockIdx.x * blockDim.x + threadIdx.x;
    int lane = threadIdx.x & 31;
    int c = (i < N_NODES) ? g_ecnt[i] : 0;
    int alloc = (c + 3) & ~3;          // pad to multiple of 4 -> 16B-aligned segments
    int incl = alloc;
    #pragma unroll
    for (int off = 1; off < 32; off <<= 1) {
        int v = __shfl_up_sync(0xffffffffu, incl, off);
        if (lane >= off) incl += v;
    }
    int excl = incl - alloc;
    int wsum = __shfl_sync(0xffffffffu, incl, 31);
    int wbase = 0;
    if (lane == 31) wbase = atomicAdd(&g_tot, wsum);
    wbase = __shfl_sync(0xffffffffu, wbase, 31);
    if (i < N_NODES) g_base[i] = wbase + excl;
}

// -------- merged: CSR fill (4 edges/thread, blocks [0,NB_FILL)) + lin0 --------
#define NB_FILL ((N_EDGES / 4 + 255) / 256)
#define NB_L0   ((N_NODES * 16 + 255) / 256)
__global__ void __launch_bounds__(256) k_fill_lin0(const int* __restrict__ ei,
                                                   const float* __restrict__ x,
                                                   const float* __restrict__ W0) {
    if (blockIdx.x < NB_FILL) {
        int idx = blockIdx.x * blockDim.x + threadIdx.x;       // < E/4
        if (idx >= N_EDGES / 4) return;
        int4 s = ((const int4*)ei)[idx];
        int4 d = ((const int4*)(ei + N_EDGES))[idx];
        int p0 = atomicAdd(&g_base[d.x], 1);
        int p1 = atomicAdd(&g_base[d.y], 1);
        int p2 = atomicAdd(&g_base[d.z], 1);
        int p3 = atomicAdd(&g_base[d.w], 1);
        g_col[p0] = s.x; g_col[p1] = s.y; g_col[p2] = s.z; g_col[p3] = s.w;
    } else {
        __shared__ float sW[D_IN * HID];
        int t = threadIdx.x;
        if (t < D_IN * HID) sW[t] = W0[t];
        __syncthreads();
        int idx = (blockIdx.x - NB_FILL) * blockDim.x + t;     // < N*16
        if (idx >= N_NODES * 16) return;
        int i = idx >> 4, j4 = idx & 15;
        float x0 = x[i * 3 + 0], x1 = x[i * 3 + 1], x2 = x[i * 3 + 2];
        float d = rsqrtf((float)(g_ecnt[i] + 1));
        float o[4];
        #pragma unroll
        for (int q = 0; q < 4; q++) {
            int j = 4 * j4 + q;
            o[q] = (x0 * sW[j] + x1 * sW[64 + j] + x2 * sW[128 + j]) * d;
        }
        uint2 pk;
        pk.x = h2_bits(__floats2half2_rn(o[0], o[1]));
        pk.y = h2_bits(__floats2half2_rn(o[2], o[3]));
        ((uint2*)g_xwh)[idx] = pk;
    }
}

// -------- hidden linear: register-tiled GEMM, 64x64/block, fp16 output -------
__global__ void __launch_bounds__(256) k_linh(const float* __restrict__ W) {
    __shared__ float sW [HID * HID];   // k-major: sW[k*64 + j]
    __shared__ float shT[HID * HID];   // transposed: shT[k*64 + node]
    int t = threadIdx.x;
    int node0 = blockIdx.x * 64;

    for (int q = t; q < 1024; q += 256)
        ((float4*)sW)[q] = ((const float4*)W)[q];

    int ln = t & 63;
    int c0 = t >> 6;
    #pragma unroll
    for (int cc = c0; cc < 16; cc += 4) {
        int gi = node0 + ln;
        float4 v = make_float4(0.f, 0.f, 0.f, 0.f);
        if (gi < N_NODES) v = ((const float4*)g_h)[gi * 16 + cc];
        shT[(4 * cc + 0) * 64 + ln] = v.x;
        shT[(4 * cc + 1) * 64 + ln] = v.y;
        shT[(4 * cc + 2) * 64 + ln] = v.z;
        shT[(4 * cc + 3) * 64 + ln] = v.w;
    }
    __syncthreads();

    int a = t >> 4;
    int b = t & 15;
    float4 acc0 = make_float4(0.f, 0.f, 0.f, 0.f);
    float4 acc1 = acc0, acc2 = acc0, acc3 = acc0;

    #pragma unroll 8
    for (int k = 0; k < 64; k++) {
        float4 vN = *(const float4*)&shT[k * 64 + 4 * a];
        float4 vW = *(const float4*)&sW [k * 64 + 4 * b];
        acc0.x += vN.x * vW.x; acc0.y += vN.x * vW.y; acc0.z += vN.x * vW.z; acc0.w += vN.x * vW.w;
        acc1.x += vN.y * vW.x; acc1.y += vN.y * vW.y; acc1.z += vN.y * vW.z; acc1.w += vN.y * vW.w;
        acc2.x += vN.z * vW.x; acc2.y += vN.z * vW.y; acc2.z += vN.z * vW.z; acc2.w += vN.z * vW.w;
        acc3.x += vN.w * vW.x; acc3.y += vN.w * vW.y; acc3.z += vN.w * vW.z; acc3.w += vN.w * vW.w;
    }

    float4 accs[4] = {acc0, acc1, acc2, acc3};
    #pragma unroll
    for (int r = 0; r < 4; r++) {
        int i = node0 + 4 * a + r;
        if (i < N_NODES) {
            float d = rsqrtf((float)(g_ecnt[i] + 1));
            float4 o = accs[r];
            uint2 pk;
            pk.x = h2_bits(__floats2half2_rn(o.x * d, o.y * d));
            pk.y = h2_bits(__floats2half2_rn(o.z * d, o.w * d));
            ((uint2*)g_xwh)[i * 16 + b] = pk;
        }
    }
}

// -------- CSR gather: 16 thr/node, uint2 rows, 8 edges in flight, fused BN ----
__global__ void __launch_bounds__(128) k_gather(const float* __restrict__ bb,
                                                const float* __restrict__ gamma,
                                                const float* __restrict__ beta,
                                                const float* __restrict__ mean,
                                                const float* __restrict__ var, int relu) {
    int t = threadIdx.x;
    int node = blockIdx.x * 8 + (t >> 4);    // N divisible by 8
    int j4 = t & 15;
    const uint2* xw2 = (const uint2*)g_xwh;

    int cnt  = g_ecnt[node];
    int base = g_base[node] - cnt;           // start (4-aligned)

    uint2 self = xw2[node * 16 + j4];
    float2 slo = __half22float2(bits_h2(self.x));
    float2 shi = __half22float2(bits_h2(self.y));
    float4 acc = make_float4(slo.x, slo.y, shi.x, shi.y);

    const int4* c4p = (const int4*)(g_col + base);   // 16B-aligned
    int k = 0;
    for (; k + 8 <= cnt; k += 8) {
        int4 ca = __ldg(&c4p[(k >> 2) + 0]);
        int4 cb = __ldg(&c4p[(k >> 2) + 1]);
        uint2 r0 = __ldg(&xw2[ca.x * 16 + j4]);
        uint2 r1 = __ldg(&xw2[ca.y * 16 + j4]);
        uint2 r2 = __ldg(&xw2[ca.z * 16 + j4]);
        uint2 r3 = __ldg(&xw2[ca.w * 16 + j4]);
        uint2 r4 = __ldg(&xw2[cb.x * 16 + j4]);
        uint2 r5 = __ldg(&xw2[cb.y * 16 + j4]);
        uint2 r6 = __ldg(&xw2[cb.z * 16 + j4]);
        uint2 r7 = __ldg(&xw2[cb.w * 16 + j4]);
        __half2 lo = __hadd2(__hadd2(__hadd2(bits_h2(r0.x), bits_h2(r1.x)),
                                     __hadd2(bits_h2(r2.x), bits_h2(r3.x))),
                             __hadd2(__hadd2(bits_h2(r4.x), bits_h2(r5.x)),
                                     __hadd2(bits_h2(r6.x), bits_h2(r7.x))));
        __half2 hi = __hadd2(__hadd2(__hadd2(bits_h2(r0.y), bits_h2(r1.y)),
                                     __hadd2(bits_h2(r2.y), bits_h2(r3.y))),
                             __hadd2(__hadd2(bits_h2(r4.y), bits_h2(r5.y)),
                                     __hadd2(bits_h2(r6.y), bits_h2(r7.y))));
        float2 flo = __half22float2(lo);
        float2 fhi = __half22float2(hi);
        acc.x += flo.x; acc.y += flo.y; acc.z += fhi.x; acc.w += fhi.y;
    }
    for (; k + 4 <= cnt; k += 4) {
        int4 c4 = __ldg(&c4p[k >> 2]);
        uint2 r0 = __ldg(&xw2[c4.x * 16 + j4]);
        uint2 r1 = __ldg(&xw2[c4.y * 16 + j4]);
        uint2 r2 = __ldg(&xw2[c4.z * 16 + j4]);
        uint2 r3 = __ldg(&xw2[c4.w * 16 + j4]);
        __half2 lo = __hadd2(__hadd2(bits_h2(r0.x), bits_h2(r1.x)),
                             __hadd2(bits_h2(r2.x), bits_h2(r3.x)));
        __half2 hi = __hadd2(__hadd2(bits_h2(r0.y), bits_h2(r1.y)),
                             __hadd2(bits_h2(r2.y), bits_h2(r3.y)));
        float2 flo = __half22float2(lo);
        float2 fhi = __half22float2(hi);
        acc.x += flo.x; acc.y += flo.y; acc.z += fhi.x; acc.w += fhi.y;
    }
    for (; k < cnt; k++) {
        int s = __ldg(&g_col[base + k]);
        uint2 r = __ldg(&xw2[s * 16 + j4]);
        float2 a = __half22float2(bits_h2(r.x));
        float2 b = __half22float2(bits_h2(r.y));
        acc.x += a.x; acc.y += a.y; acc.z += b.x; acc.w += b.y;
    }

    float d = rsqrtf((float)(cnt + 1));
    float4 vb  = ((const float4*)bb)[j4];
    float4 vg  = ((const float4*)gamma)[j4];
    float4 vbt = ((const float4*)beta)[j4];
    float4 vm  = ((const float4*)mean)[j4];
    float4 vv  = ((const float4*)var)[j4];
    float4 o;
    o.x = (acc.x * d + vb.x - vm.x) * (vg.x * rsqrtf(vv.x + EPS_BN)) + vbt.x;
    o.y = (acc.y * d + vb.y - vm.y) * (vg.y * rsqrtf(vv.y + EPS_BN)) + vbt.y;
    o.z = (acc.z * d + vb.z - vm.z) * (vg.z * rsqrtf(vv.z + EPS_BN)) + vbt.z;
    o.w = (acc.w * d + vb.w - vm.w) * (vg.w * rsqrtf(vv.w + EPS_BN)) + vbt.w;
    if (relu) {
        o.x = fmaxf(o.x, 0.f); o.y = fmaxf(o.y, 0.f);
        o.z = fmaxf(o.z, 0.f); o.w = fmaxf(o.w, 0.f);
    }
    ((float4*)g_h)[node * 16 + j4] = o;
}

// -------- fused pooling + classifier + log_softmax: 1 block / graph -----------
__global__ void __launch_bounds__(256) k_poolcls(const int* __restrict__ batch,
                                                 const float* __restrict__ Wc1,
                                                 const float* __restrict__ bc1,
                                                 const float* __restrict__ Wc2,
                                                 const float* __restrict__ bc2,
                                                 float* __restrict__ out) {
    __shared__ int s_se[2];
    __shared__ float ssum[16 * 65];
    __shared__ float smax[16 * 65];
    __shared__ float gv[2 * HID];
    __shared__ float hc[HID];
    __shared__ float lg[C_OUT];
    __shared__ float s_lse;

    int g = blockIdx.x;
    int t = threadIdx.x;

    if (t == 0) {
        int lo = 0, hi = N_NODES;
        while (lo < hi) { int m = (lo + hi) >> 1; if (batch[m] < g) lo = m + 1; else hi = m; }
        s_se[0] = lo;
        lo = 0; hi = N_NODES;
        while (lo < hi) { int m = (lo + hi) >> 1; if (batch[m] < g + 1) lo = m + 1; else hi = m; }
        s_se[1] = lo;
    }
    __syncthreads();
    int start = s_se[0], end = s_se[1];

    int r  = t >> 4;
    int j4 = t & 15;
    const float4* h4 = (const float4*)g_h;
    float4 sum = make_float4(0.f, 0.f, 0.f, 0.f);
    float4 mx  = make_float4(-INFINITY, -INFINITY, -INFINITY, -INFINITY);
    for (int i = start + r; i < end; i += 16) {
        float4 v = h4[i * 16 + j4];
        sum.x += v.x; sum.y += v.y; sum.z += v.z; sum.w += v.w;
        mx.x = fmaxf(mx.x, v.x); mx.y = fmaxf(mx.y, v.y);
        mx.z = fmaxf(mx.z, v.z); mx.w = fmaxf(mx.w, v.w);
    }
    ssum[r * 65 + 4 * j4 + 0] = sum.x; ssum[r * 65 + 4 * j4 + 1] = sum.y;
    ssum[r * 65 + 4 * j4 + 2] = sum.z; ssum[r * 65 + 4 * j4 + 3] = sum.w;
    smax[r * 65 + 4 * j4 + 0] = mx.x;  smax[r * 65 + 4 * j4 + 1] = mx.y;
    smax[r * 65 + 4 * j4 + 2] = mx.z;  smax[r * 65 + 4 * j4 + 3] = mx.w;
    __syncthreads();

    if (t < HID) {
        float s = 0.f, m = -INFINITY;
        #pragma unroll
        for (int q = 0; q < 16; q++) {
            s += ssum[q * 65 + t];
            m = fmaxf(m, smax[q * 65 + t]);
        }
        gv[t]       = s / (float)(end - start);
        gv[HID + t] = m;
    }
    __syncthreads();

    if (t < HID) {
        float s = bc1[t];
        #pragma unroll 16
        for (int k = 0; k < 2 * HID; k++) s += gv[k] * Wc1[k * HID + t];
        hc[t] = fmaxf(s, 0.f);
    }
    __syncthreads();

    if (t < C_OUT) {
        float l = bc2[t];
        #pragma unroll 16
        for (int j = 0; j < HID; j++) l += hc[j] * Wc2[j * C_OUT + t];
        lg[t] = l;
    }
    __syncthreads();

    if (t == 0) {
        float m = -INFINITY;
        #pragma unroll
        for (int c = 0; c < C_OUT; c++) m = fmaxf(m, lg[c]);
        float se = 0.f;
        #pragma unroll
        for (int c = 0; c < C_OUT; c++) se += expf(lg[c] - m);
        s_lse = m + logf(se);
    }
    __syncthreads();
    if (t < C_OUT) out[g * C_OUT + t] = lg[t] - s_lse;
}

extern "C" void kernel_launch(void* const* d_in, const int* in_sizes, int n_in,
                              void* d_out, int out_size) {
    const float* x     = (const float*)d_in[0];
    const int*   ei    = (const int*)  d_in[1];
    const int*   batch = (const int*)  d_in[2];
    // d_in[3] = num_graphs (constant 128, unused)
    const float* W0    = (const float*)d_in[4];
    const float* Ws    = (const float*)d_in[5];
    const float* bs    = (const float*)d_in[6];
    const float* gamma = (const float*)d_in[7];
    const float* beta  = (const float*)d_in[8];
    const float* rmean = (const float*)d_in[9];
    const float* rvar  = (const float*)d_in[10];
    const float* Wc1   = (const float*)d_in[11];
    const float* bc1   = (const float*)d_in[12];
    const float* Wc2   = (const float*)d_in[13];
    const float* bc2   = (const float*)d_in[14];
    float* out = (float*)d_out;

    const int NB_N    = (N_NODES + 255) / 256;
    const int NB_E4   = (N_EDGES / 4 + 255) / 256;
    const int NB_GAT  = N_NODES / 8;           // 12500, 128-thread blocks
    const int NB_GEMM = (N_NODES + 63) / 64;

    // zero-init counters via graph memset nodes
    void* p_ecnt = 0; void* p_tot = 0;
    cudaGetSymbolAddress(&p_ecnt, g_ecnt);
    cudaGetSymbolAddress(&p_tot,  g_tot);
    cudaMemsetAsync(p_ecnt, 0, N_NODES * sizeof(int));
    cudaMemsetAsync(p_tot,  0, sizeof(int));

    // CSR build (fill overlapped with layer-0 linear in one launch)
    k_deg      <<<NB_E4, 256>>>(ei);
    k_base     <<<NB_N, 256>>>();
    k_fill_lin0<<<NB_FILL + NB_L0, 256>>>(ei, x, W0);

    // layer 0 aggregate
    k_gather<<<NB_GAT, 128>>>(bs + 0 * HID, gamma + 0 * HID, beta + 0 * HID,
                              rmean + 0 * HID, rvar + 0 * HID, 1);
    // layer 1
    k_linh  <<<NB_GEMM, 256>>>(Ws + 0 * HID * HID);
    k_gather<<<NB_GAT, 128>>>(bs + 1 * HID, gamma + 1 * HID, beta + 1 * HID,
                              rmean + 1 * HID, rvar + 1 * HID, 1);
    // layer 2 (no relu)
    k_linh  <<<NB_GEMM, 256>>>(Ws + 1 * HID * HID);
    k_gather<<<NB_GAT, 128>>>(bs + 2 * HID, gamma + 2 * HID, beta + 2 * HID,
                              rmean + 2 * HID, rvar + 2 * HID, 0);

    // fused pooling + classifier
    k_poolcls<<<G_NUM, 256>>>(batch, Wc1, bc1, Wc2, bc2, out);
}

// round 16
// speedup vs baseline: 1.1247x; 1.0114x over previous
#include <cuda_runtime.h>
#include <cuda_fp16.h>
#include <math.h>

#define N_NODES 100000
#define N_EDGES 1200000
#define COL_CAP (N_EDGES + 3 * N_NODES + 16)
#define HID 64
#define G_NUM 128
#define C_OUT 10
#define D_IN 3
#define EPS_BN 1e-5f

static __device__ __forceinline__ unsigned int h2_bits(__half2 h) {
    return *reinterpret_cast<unsigned int*>(&h);
}
static __device__ __forceinline__ __half2 bits_h2(unsigned int u) {
    return *reinterpret_cast<__half2*>(&u);
}

// -------- scratch (static device globals; no runtime allocation) --------
__device__ int   g_ecnt[N_NODES];
__device__ int   g_base[N_NODES];     // after k_base: aligned start; after fill: start+cnt
__device__ __align__(16) int g_col[COL_CAP];
__device__ int   g_tot;
__device__ __align__(16) __half g_xwh[N_NODES * HID];   // (h@W)*dinv, fp16
__device__ __align__(16) float  g_h  [N_NODES * HID];   // layer output, fp32

// -------- in-degree over real edges (4 edges/thread via int4) --------
__global__ void __launch_bounds__(256) k_deg(const int* __restrict__ ei) {
    int idx = blockIdx.x * blockDim.x + threadIdx.x;           // < E/4
    if (idx >= N_EDGES / 4) return;
    int4 d = ((const int4*)(ei + N_EDGES))[idx];
    atomicAdd(&g_ecnt[d.x], 1);
    atomicAdd(&g_ecnt[d.y], 1);
    atomicAdd(&g_ecnt[d.z], 1);
    atomicAdd(&g_ecnt[d.w], 1);
}

// -------- CSR bases, 4-aligned allocations (warp scan + atomic) --------
__global__ void k_base() {
    int i = blockIdx.x * blockDim.x + threadIdx.x;
    int lane = threadIdx.x & 31;
    int c = (i < N_NODES) ? g_ecnt[i] : 0;
    int alloc = (c + 3) & ~3;          // pad to multiple of 4 -> 16B-aligned segments
    int incl = alloc;
    #pragma unroll
    for (int off = 1; off < 32; off <<= 1) {
        int v = __shfl_up_sync(0xffffffffu, incl, off);
        if (lane >= off) incl += v;
    }
    int excl = incl - alloc;
    int wsum = __shfl_sync(0xffffffffu, incl, 31);
    int wbase = 0;
    if (lane == 31) wbase = atomicAdd(&g_tot, wsum);
    wbase = __shfl_sync(0xffffffffu, wbase, 31);
    if (i < N_NODES) g_base[i] = wbase + excl;
}

// -------- merged: CSR fill (4 edges/thread, blocks [0,NB_FILL)) + lin0 --------
#define NB_FILL ((N_EDGES / 4 + 255) / 256)
#define NB_L0   ((N_NODES * 16 + 255) / 256)
__global__ void __launch_bounds__(256) k_fill_lin0(const int* __restrict__ ei,
                                                   const float* __restrict__ x,
                                                   const float* __restrict__ W0) {
    if (blockIdx.x < NB_FILL) {
        int idx = blockIdx.x * blockDim.x + threadIdx.x;       // < E/4
        if (idx >= N_EDGES / 4) return;
        int4 s = ((const int4*)ei)[idx];
        int4 d = ((const int4*)(ei + N_EDGES))[idx];
        int p0 = atomicAdd(&g_base[d.x], 1);
        int p1 = atomicAdd(&g_base[d.y], 1);
        int p2 = atomicAdd(&g_base[d.z], 1);
        int p3 = atomicAdd(&g_base[d.w], 1);
        g_col[p0] = s.x; g_col[p1] = s.y; g_col[p2] = s.z; g_col[p3] = s.w;
    } else {
        __shared__ float sW[D_IN * HID];
        int t = threadIdx.x;
        if (t < D_IN * HID) sW[t] = W0[t];
        __syncthreads();
        int idx = (blockIdx.x - NB_FILL) * blockDim.x + t;     // < N*16
        if (idx >= N_NODES * 16) return;
        int i = idx >> 4, j4 = idx & 15;
        float x0 = x[i * 3 + 0], x1 = x[i * 3 + 1], x2 = x[i * 3 + 2];
        float d = rsqrtf((float)(g_ecnt[i] + 1));
        float o[4];
        #pragma unroll
        for (int q = 0; q < 4; q++) {
            int j = 4 * j4 + q;
            o[q] = (x0 * sW[j] + x1 * sW[64 + j] + x2 * sW[128 + j]) * d;
        }
        uint2 pk;
        pk.x = h2_bits(__floats2half2_rn(o[0], o[1]));
        pk.y = h2_bits(__floats2half2_rn(o[2], o[3]));
        ((uint2*)g_xwh)[idx] = pk;
    }
}

// -------- hidden linear: register-tiled GEMM, 64x64/block, fp16 output -------
__global__ void __launch_bounds__(256) k_linh(const float* __restrict__ W) {
    __shared__ float sW [HID * HID];   // k-major: sW[k*64 + j]
    __shared__ float shT[HID * HID];   // transposed: shT[k*64 + node]
    int t = threadIdx.x;
    int node0 = blockIdx.x * 64;

    for (int q = t; q < 1024; q += 256)
        ((float4*)sW)[q] = ((const float4*)W)[q];

    int ln = t & 63;
    int c0 = t >> 6;
    #pragma unroll
    for (int cc = c0; cc < 16; cc += 4) {
        int gi = node0 + ln;
        float4 v = make_float4(0.f, 0.f, 0.f, 0.f);
        if (gi < N_NODES) v = ((const float4*)g_h)[gi * 16 + cc];
        shT[(4 * cc + 0) * 64 + ln] = v.x;
        shT[(4 * cc + 1) * 64 + ln] = v.y;
        shT[(4 * cc + 2) * 64 + ln] = v.z;
        shT[(4 * cc + 3) * 64 + ln] = v.w;
    }
    __syncthreads();

    int a = t >> 4;
    int b = t & 15;
    float4 acc0 = make_float4(0.f, 0.f, 0.f, 0.f);
    float4 acc1 = acc0, acc2 = acc0, acc3 = acc0;

    #pragma unroll 8
    for (int k = 0; k < 64; k++) {
        float4 vN = *(const float4*)&shT[k * 64 + 4 * a];
        float4 vW = *(const float4*)&sW [k * 64 + 4 * b];
        acc0.x += vN.x * vW.x; acc0.y += vN.x * vW.y; acc0.z += vN.x * vW.z; acc0.w += vN.x * vW.w;
        acc1.x += vN.y * vW.x; acc1.y += vN.y * vW.y; acc1.z += vN.y * vW.z; acc1.w += vN.y * vW.w;
        acc2.x += vN.z * vW.x; acc2.y += vN.z * vW.y; acc2.z += vN.z * vW.z; acc2.w += vN.z * vW.w;
        acc3.x += vN.w * vW.x; acc3.y += vN.w * vW.y; acc3.z += vN.w * vW.z; acc3.w += vN.w * vW.w;
    }

    float4 accs[4] = {acc0, acc1, acc2, acc3};
    #pragma unroll
    for (int r = 0; r < 4; r++) {
        int i = node0 + 4 * a + r;
        if (i < N_NODES) {
            float d = rsqrtf((float)(g_ecnt[i] + 1));
            float4 o = accs[r];
            uint2 pk;
            pk.x = h2_bits(__floats2half2_rn(o.x * d, o.y * d));
            pk.y = h2_bits(__floats2half2_rn(o.z * d, o.w * d));
            ((uint2*)g_xwh)[i * 16 + b] = pk;
        }
    }
}

// -------- CSR gather: 16 thr/node, uint2 rows, 8 in flight; occupancy-forced --
__global__ void __launch_bounds__(128, 16) k_gather(const float* __restrict__ bb,
                                                    const float* __restrict__ gamma,
                                                    const float* __restrict__ beta,
                                                    const float* __restrict__ mean,
                                                    const float* __restrict__ var,
                                                    int relu) {
    int t = threadIdx.x;
    int node = blockIdx.x * 8 + (t >> 4);    // N divisible by 8
    int j4 = t & 15;
    const uint2* xw2 = (const uint2*)g_xwh;

    int cnt  = g_ecnt[node];
    int base = g_base[node] - cnt;           // start (4-aligned)

    uint2 self = xw2[node * 16 + j4];
    float2 slo = __half22float2(bits_h2(self.x));
    float2 shi = __half22float2(bits_h2(self.y));
    float4 acc = make_float4(slo.x, slo.y, shi.x, shi.y);

    const int4* c4p = (const int4*)(g_col + base);   // 16B-aligned
    int k = 0;
    for (; k + 8 <= cnt; k += 8) {
        int4 ca = __ldg(&c4p[(k >> 2) + 0]);
        int4 cb = __ldg(&c4p[(k >> 2) + 1]);
        uint2 r0 = __ldg(&xw2[ca.x * 16 + j4]);
        uint2 r1 = __ldg(&xw2[ca.y * 16 + j4]);
        uint2 r2 = __ldg(&xw2[ca.z * 16 + j4]);
        uint2 r3 = __ldg(&xw2[ca.w * 16 + j4]);
        uint2 r4 = __ldg(&xw2[cb.x * 16 + j4]);
        uint2 r5 = __ldg(&xw2[cb.y * 16 + j4]);
        uint2 r6 = __ldg(&xw2[cb.z * 16 + j4]);
        uint2 r7 = __ldg(&xw2[cb.w * 16 + j4]);
        __half2 lo = __hadd2(__hadd2(__hadd2(bits_h2(r0.x), bits_h2(r1.x)),
                                     __hadd2(bits_h2(r2.x), bits_h2(r3.x))),
                             __hadd2(__hadd2(bits_h2(r4.x), bits_h2(r5.x)),
                                     __hadd2(bits_h2(r6.x), bits_h2(r7.x))));
        __half2 hi = __hadd2(__hadd2(__hadd2(bits_h2(r0.y), bits_h2(r1.y)),
                                     __hadd2(bits_h2(r2.y), bits_h2(r3.y))),
                             __hadd2(__hadd2(bits_h2(r4.y), bits_h2(r5.y)),
                                     __hadd2(bits_h2(r6.y), bits_h2(r7.y))));
        float2 flo = __half22float2(lo);
        float2 fhi = __half22float2(hi);
        acc.x += flo.x; acc.y += flo.y; acc.z += fhi.x; acc.w += fhi.y;
    }
    for (; k + 4 <= cnt; k += 4) {
        int4 c4 = __ldg(&c4p[k >> 2]);
        uint2 r0 = __ldg(&xw2[c4.x * 16 + j4]);
        uint2 r1 = __ldg(&xw2[c4.y * 16 + j4]);
        uint2 r2 = __ldg(&xw2[c4.z * 16 + j4]);
        uint2 r3 = __ldg(&xw2[c4.w * 16 + j4]);
        __half2 lo = __hadd2(__hadd2(bits_h2(r0.x), bits_h2(r1.x)),
                             __hadd2(bits_h2(r2.x), bits_h2(r3.x)));
        __half2 hi = __hadd2(__hadd2(bits_h2(r0.y), bits_h2(r1.y)),
                             __hadd2(bits_h2(r2.y), bits_h2(r3.y)));
        float2 flo = __half22float2(lo);
        float2 fhi = __half22float2(hi);
        acc.x += flo.x; acc.y += flo.y; acc.z += fhi.x; acc.w += fhi.y;
    }
    for (; k < cnt; k++) {
        int s = __ldg(&g_col[base + k]);
        uint2 r = __ldg(&xw2[s * 16 + j4]);
        float2 a = __half22float2(bits_h2(r.x));
        float2 b = __half22float2(bits_h2(r.y));
        acc.x += a.x; acc.y += a.y; acc.z += b.x; acc.w += b.y;
    }

    float d = rsqrtf((float)(cnt + 1));
    float4 vb  = ((const float4*)bb)[j4];
    float4 vg  = ((const float4*)gamma)[j4];
    float4 vbt = ((const float4*)beta)[j4];
    float4 vm  = ((const float4*)mean)[j4];
    float4 vv  = ((const float4*)var)[j4];
    float4 o;
    o.x = (acc.x * d + vb.x - vm.x) * (vg.x * rsqrtf(vv.x + EPS_BN)) + vbt.x;
    o.y = (acc.y * d + vb.y - vm.y) * (vg.y * rsqrtf(vv.y + EPS_BN)) + vbt.y;
    o.z = (acc.z * d + vb.z - vm.z) * (vg.z * rsqrtf(vv.z + EPS_BN)) + vbt.z;
    o.w = (acc.w * d + vb.w - vm.w) * (vg.w * rsqrtf(vv.w + EPS_BN)) + vbt.w;
    if (relu) {
        o.x = fmaxf(o.x, 0.f); o.y = fmaxf(o.y, 0.f);
        o.z = fmaxf(o.z, 0.f); o.w = fmaxf(o.w, 0.f);
    }
    ((float4*)g_h)[node * 16 + j4] = o;
}

// -------- fused pooling + classifier + log_softmax: 1 block / graph -----------
__global__ void __launch_bounds__(256) k_poolcls(const int* __restrict__ batch,
                                                 const float* __restrict__ Wc1,
                                                 const float* __restrict__ bc1,
                                                 const float* __restrict__ Wc2,
                                                 const float* __restrict__ bc2,
                                                 float* __restrict__ out) {
    __shared__ int s_se[2];
    __shared__ float ssum[16 * 65];
    __shared__ float smax[16 * 65];
    __shared__ float gv[2 * HID];
    __shared__ float hc[HID];
    __shared__ float lg[C_OUT];
    __shared__ float s_lse;

    int g = blockIdx.x;
    int t = threadIdx.x;

    if (t == 0) {
        int lo = 0, hi = N_NODES;
        while (lo < hi) { int m = (lo + hi) >> 1; if (batch[m] < g) lo = m + 1; else hi = m; }
        s_se[0] = lo;
        lo = 0; hi = N_NODES;
        while (lo < hi) { int m = (lo + hi) >> 1; if (batch[m] < g + 1) lo = m + 1; else hi = m; }
        s_se[1] = lo;
    }
    __syncthreads();
    int start = s_se[0], end = s_se[1];

    int r  = t >> 4;
    int j4 = t & 15;
    const float4* h4 = (const float4*)g_h;
    float4 sum = make_float4(0.f, 0.f, 0.f, 0.f);
    float4 mx  = make_float4(-INFINITY, -INFINITY, -INFINITY, -INFINITY);
    for (int i = start + r; i < end; i += 16) {
        float4 v = h4[i * 16 + j4];
        sum.x += v.x; sum.y += v.y; sum.z += v.z; sum.w += v.w;
        mx.x = fmaxf(mx.x, v.x); mx.y = fmaxf(mx.y, v.y);
        mx.z = fmaxf(mx.z, v.z); mx.w = fmaxf(mx.w, v.w);
    }
    ssum[r * 65 + 4 * j4 + 0] = sum.x; ssum[r * 65 + 4 * j4 + 1] = sum.y;
    ssum[r * 65 + 4 * j4 + 2] = sum.z; ssum[r * 65 + 4 * j4 + 3] = sum.w;
    smax[r * 65 + 4 * j4 + 0] = mx.x;  smax[r * 65 + 4 * j4 + 1] = mx.y;
    smax[r * 65 + 4 * j4 + 2] = mx.z;  smax[r * 65 + 4 * j4 + 3] = mx.w;
    __syncthreads();

    if (t < HID) {
        float s = 0.f, m = -INFINITY;
        #pragma unroll
        for (int q = 0; q < 16; q++) {
            s += ssum[q * 65 + t];
            m = fmaxf(m, smax[q * 65 + t]);
        }
        gv[t]       = s / (float)(end - start);
        gv[HID + t] = m;
    }
    __syncthreads();

    if (t < HID) {
        float s = bc1[t];
        #pragma unroll 16
        for (int k = 0; k < 2 * HID; k++) s += gv[k] * Wc1[k * HID + t];
        hc[t] = fmaxf(s, 0.f);
    }
    __syncthreads();

    if (t < C_OUT) {
        float l = bc2[t];
        #pragma unroll 16
        for (int j = 0; j < HID; j++) l += hc[j] * Wc2[j * C_OUT + t];
        lg[t] = l;
    }
    __syncthreads();

    if (t == 0) {
        float m = -INFINITY;
        #pragma unroll
        for (int c = 0; c < C_OUT; c++) m = fmaxf(m, lg[c]);
        float se = 0.f;
        #pragma unroll
        for (int c = 0; c < C_OUT; c++) se += expf(lg[c] - m);
        s_lse = m + logf(se);
    }
    __syncthreads();
    if (t < C_OUT) out[g * C_OUT + t] = lg[t] - s_lse;
}

extern "C" void kernel_launch(void* const* d_in, const int* in_sizes, int n_in,
                              void* d_out, int out_size) {
    const float* x     = (const float*)d_in[0];
    const int*   ei    = (const int*)  d_in[1];
    const int*   batch = (const int*)  d_in[2];
    // d_in[3] = num_graphs (constant 128, unused)
    const float* W0    = (const float*)d_in[4];
    const float* Ws    = (const float*)d_in[5];
    const float* bs    = (const float*)d_in[6];
    const float* gamma = (const float*)d_in[7];
    const float* beta  = (const float*)d_in[8];
    const float* rmean = (const float*)d_in[9];
    const float* rvar  = (const float*)d_in[10];
    const float* Wc1   = (const float*)d_in[11];
    const float* bc1   = (const float*)d_in[12];
    const float* Wc2   = (const float*)d_in[13];
    const float* bc2   = (const float*)d_in[14];
    float* out = (float*)d_out;

    const int NB_N    = (N_NODES + 255) / 256;
    const int NB_E4   = (N_EDGES / 4 + 255) / 256;
    const int NB_GAT  = N_NODES / 8;           // 12500, 128-thread blocks
    const int NB_GEMM = (N_NODES + 63) / 64;

    // zero-init counters via graph memset nodes
    void* p_ecnt = 0; void* p_tot = 0;
    cudaGetSymbolAddress(&p_ecnt, g_ecnt);
    cudaGetSymbolAddress(&p_tot,  g_tot);
    cudaMemsetAsync(p_ecnt, 0, N_NODES * sizeof(int));
    cudaMemsetAsync(p_tot,  0, sizeof(int));

    // CSR build (fill overlapped with layer-0 linear in one launch)
    k_deg      <<<NB_E4, 256>>>(ei);
    k_base     <<<NB_N, 256>>>();
    k_fill_lin0<<<NB_FILL + NB_L0, 256>>>(ei, x, W0);

    // layer 0 aggregate
    k_gather<<<NB_GAT, 128>>>(bs + 0 * HID, gamma + 0 * HID, beta + 0 * HID,
                              rmean + 0 * HID, rvar + 0 * HID, 1);
    // layer 1
    k_linh  <<<NB_GEMM, 256>>>(Ws + 0 * HID * HID);
    k_gather<<<NB_GAT, 128>>>(bs + 1 * HID, gamma + 1 * HID, beta + 1 * HID,
                              rmean + 1 * HID, rvar + 1 * HID, 1);
    // layer 2 (no relu)
    k_linh  <<<NB_GEMM, 256>>>(Ws + 1 * HID * HID);
    k_gather<<<NB_GAT, 128>>>(bs + 2 * HID, gamma + 2 * HID, beta + 2 * HID,
                              rmean + 2 * HID, rvar + 2 * HID, 0);

    // fused pooling + classifier
    k_poolcls<<<G_NUM, 256>>>(batch, Wc1, bc1, Wc2, bc2, out);
}

// round 17
// speedup vs baseline: 1.1916x; 1.0595x over previous
#include <cuda_runtime.h>
#include <cuda_fp16.h>
#include <math.h>

#define N_NODES 100000
#define N_EDGES 1200000
#define COL_CAP (N_EDGES + 3 * N_NODES + 16)
#define HID 64
#define G_NUM 128
#define C_OUT 10
#define D_IN 3
#define EPS_BN 1e-5f

static __device__ __forceinline__ unsigned int h2_bits(__half2 h) {
    return *reinterpret_cast<unsigned int*>(&h);
}
static __device__ __forceinline__ __half2 bits_h2(unsigned int u) {
    return *reinterpret_cast<__half2*>(&u);
}

// -------- scratch (static device globals; no runtime allocation) --------
__device__ int   g_ecnt[N_NODES];
__device__ int   g_base[N_NODES];     // after k_base: aligned start; after fill: start+cnt
__device__ __align__(16) int g_col[COL_CAP];
__device__ int   g_tot;
__device__ __align__(16) __half g_xwh[N_NODES * HID];   // (h@W)*dinv, fp16
__device__ __align__(16) float  g_h  [N_NODES * HID];   // layer output, fp32

// -------- in-degree over real edges (4 edges/thread via int4) --------
__global__ void __launch_bounds__(256) k_deg(const int* __restrict__ ei) {
    int idx = blockIdx.x * blockDim.x + threadIdx.x;           // < E/4
    if (idx >= N_EDGES / 4) return;
    int4 d = ((const int4*)(ei + N_EDGES))[idx];
    atomicAdd(&g_ecnt[d.x], 1);
    atomicAdd(&g_ecnt[d.y], 1);
    atomicAdd(&g_ecnt[d.z], 1);
    atomicAdd(&g_ecnt[d.w], 1);
}

// -------- CSR bases, 4-aligned allocations (warp scan + atomic) --------
__global__ void k_base() {
    int i = blockIdx.x * blockDim.x + threadIdx.x;
    int lane = threadIdx.x & 31;
    int c = (i < N_NODES) ? g_ecnt[i] : 0;
    int alloc = (c + 3) & ~3;          // pad to multiple of 4 -> 16B-aligned segments
    int incl = alloc;
    #pragma unroll
    for (int off = 1; off < 32; off <<= 1) {
        int v = __shfl_up_sync(0xffffffffu, incl, off);
        if (lane >= off) incl += v;
    }
    int excl = incl - alloc;
    int wsum = __shfl_sync(0xffffffffu, incl, 31);
    int wbase = 0;
    if (lane == 31) wbase = atomicAdd(&g_tot, wsum);
    wbase = __shfl_sync(0xffffffffu, wbase, 31);
    if (i < N_NODES) g_base[i] = wbase + excl;
}

// -------- merged: CSR fill (4 edges/thread, blocks [0,NB_FILL)) + lin0 --------
#define NB_FILL ((N_EDGES / 4 + 255) / 256)
#define NB_L0   ((N_NODES * 16 + 255) / 256)
__global__ void __launch_bounds__(256) k_fill_lin0(const int* __restrict__ ei,
                                                   const float* __restrict__ x,
                                                   const float* __restrict__ W0) {
    if (blockIdx.x < NB_FILL) {
        int idx = blockIdx.x * blockDim.x + threadIdx.x;       // < E/4
        if (idx >= N_EDGES / 4) return;
        int4 s = ((const int4*)ei)[idx];
        int4 d = ((const int4*)(ei + N_EDGES))[idx];
        int p0 = atomicAdd(&g_base[d.x], 1);
        int p1 = atomicAdd(&g_base[d.y], 1);
        int p2 = atomicAdd(&g_base[d.z], 1);
        int p3 = atomicAdd(&g_base[d.w], 1);
        g_col[p0] = s.x; g_col[p1] = s.y; g_col[p2] = s.z; g_col[p3] = s.w;
    } else {
        __shared__ float sW[D_IN * HID];
        int t = threadIdx.x;
        if (t < D_IN * HID) sW[t] = W0[t];
        __syncthreads();
        int idx = (blockIdx.x - NB_FILL) * blockDim.x + t;     // < N*16
        if (idx >= N_NODES * 16) return;
        int i = idx >> 4, j4 = idx & 15;
        float x0 = x[i * 3 + 0], x1 = x[i * 3 + 1], x2 = x[i * 3 + 2];
        float d = rsqrtf((float)(g_ecnt[i] + 1));
        float o[4];
        #pragma unroll
        for (int q = 0; q < 4; q++) {
            int j = 4 * j4 + q;
            o[q] = (x0 * sW[j] + x1 * sW[64 + j] + x2 * sW[128 + j]) * d;
        }
        uint2 pk;
        pk.x = h2_bits(__floats2half2_rn(o[0], o[1]));
        pk.y = h2_bits(__floats2half2_rn(o[2], o[3]));
        ((uint2*)g_xwh)[idx] = pk;
    }
}

// -------- hidden linear: HFMA2 register-tiled GEMM, 64x64/block ---------------
// shT2[k][node] = duplicated half2 (v,v); sWh[k][j] fp16; fp16 partials flushed
// to fp32 every 16 k-steps.
__global__ void __launch_bounds__(256) k_linh(const float* __restrict__ W) {
    __shared__ __half2 shT2[HID * 64];   // 16KB: [k][node] (v,v)
    __shared__ __half  sWh [HID * HID];  //  8KB: k-major
    int t = threadIdx.x;
    int node0 = blockIdx.x * 64;

    // W fp32 -> fp16 (1024 float4 -> 1024 uint2)
    for (int q = t; q < 1024; q += 256) {
        float4 w = ((const float4*)W)[q];
        uint2 pk;
        pk.x = h2_bits(__floats2half2_rn(w.x, w.y));
        pk.y = h2_bits(__floats2half2_rn(w.z, w.w));
        ((uint2*)sWh)[q] = pk;
    }

    // g_h rows -> duplicated half2, transposed
    int ln = t & 63;
    int c0 = t >> 6;
    #pragma unroll
    for (int cc = c0; cc < 16; cc += 4) {
        int gi = node0 + ln;
        float4 v = make_float4(0.f, 0.f, 0.f, 0.f);
        if (gi < N_NODES) v = ((const float4*)g_h)[gi * 16 + cc];
        shT2[(4 * cc + 0) * 64 + ln] = __float2half2_rn(v.x);
        shT2[(4 * cc + 1) * 64 + ln] = __float2half2_rn(v.y);
        shT2[(4 * cc + 2) * 64 + ln] = __float2half2_rn(v.z);
        shT2[(4 * cc + 3) * 64 + ln] = __float2half2_rn(v.w);
    }
    __syncthreads();

    int a = t >> 4;   // node group: nodes 4a..4a+3
    int b = t & 15;   // col group:  cols 4b..4b+3
    float accf[4][4];
    #pragma unroll
    for (int n = 0; n < 4; n++)
        #pragma unroll
        for (int p = 0; p < 4; p++) accf[n][p] = 0.f;

    #pragma unroll
    for (int kk = 0; kk < 4; kk++) {
        __half2 acc[4][2];
        #pragma unroll
        for (int n = 0; n < 4; n++) {
            acc[n][0] = __float2half2_rn(0.f);
            acc[n][1] = __float2half2_rn(0.f);
        }
        #pragma unroll
        for (int k2 = 0; k2 < 16; k2++) {
            int k = kk * 16 + k2;
            uint4 vn = *(const uint4*)&shT2[k * 64 + 4 * a];   // 4 dup half2
            uint2 vw = *(const uint2*)&sWh [k * 64 + 4 * b];   // 4 halves
            __half2 w0 = bits_h2(vw.x), w1 = bits_h2(vw.y);
            acc[0][0] = __hfma2(bits_h2(vn.x), w0, acc[0][0]);
            acc[0][1] = __hfma2(bits_h2(vn.x), w1, acc[0][1]);
            acc[1][0] = __hfma2(bits_h2(vn.y), w0, acc[1][0]);
            acc[1][1] = __hfma2(bits_h2(vn.y), w1, acc[1][1]);
            acc[2][0] = __hfma2(bits_h2(vn.z), w0, acc[2][0]);
            acc[2][1] = __hfma2(bits_h2(vn.z), w1, acc[2][1]);
            acc[3][0] = __hfma2(bits_h2(vn.w), w0, acc[3][0]);
            acc[3][1] = __hfma2(bits_h2(vn.w), w1, acc[3][1]);
        }
        #pragma unroll
        for (int n = 0; n < 4; n++) {
            float2 f0 = __half22float2(acc[n][0]);
            float2 f1 = __half22float2(acc[n][1]);
            accf[n][0] += f0.x; accf[n][1] += f0.y;
            accf[n][2] += f1.x; accf[n][3] += f1.y;
        }
    }

    #pragma unroll
    for (int r = 0; r < 4; r++) {
        int i = node0 + 4 * a + r;
        if (i < N_NODES) {
            float d = rsqrtf((float)(g_ecnt[i] + 1));
            uint2 pk;
            pk.x = h2_bits(__floats2half2_rn(accf[r][0] * d, accf[r][1] * d));
            pk.y = h2_bits(__floats2half2_rn(accf[r][2] * d, accf[r][3] * d));
            ((uint2*)g_xwh)[i * 16 + b] = pk;
        }
    }
}

// -------- CSR gather: 16 thr/node, uint2 rows, 8 in flight; occupancy-forced --
__global__ void __launch_bounds__(128, 16) k_gather(const float* __restrict__ bb,
                                                    const float* __restrict__ gamma,
                                                    const float* __restrict__ beta,
                                                    const float* __restrict__ mean,
                                                    const float* __restrict__ var,
                                                    int relu) {
    int t = threadIdx.x;
    int node = blockIdx.x * 8 + (t >> 4);    // N divisible by 8
    int j4 = t & 15;
    const uint2* xw2 = (const uint2*)g_xwh;

    int cnt  = g_ecnt[node];
    int base = g_base[node] - cnt;           // start (4-aligned)

    uint2 self = xw2[node * 16 + j4];
    float2 slo = __half22float2(bits_h2(self.x));
    float2 shi = __half22float2(bits_h2(self.y));
    float4 acc = make_float4(slo.x, slo.y, shi.x, shi.y);

    const int4* c4p = (const int4*)(g_col + base);   // 16B-aligned
    int k = 0;
    for (; k + 8 <= cnt; k += 8) {
        int4 ca = __ldg(&c4p[(k >> 2) + 0]);
        int4 cb = __ldg(&c4p[(k >> 2) + 1]);
        uint2 r0 = __ldg(&xw2[ca.x * 16 + j4]);
        uint2 r1 = __ldg(&xw2[ca.y * 16 + j4]);
        uint2 r2 = __ldg(&xw2[ca.z * 16 + j4]);
        uint2 r3 = __ldg(&xw2[ca.w * 16 + j4]);
        uint2 r4 = __ldg(&xw2[cb.x * 16 + j4]);
        uint2 r5 = __ldg(&xw2[cb.y * 16 + j4]);
        uint2 r6 = __ldg(&xw2[cb.z * 16 + j4]);
        uint2 r7 = __ldg(&xw2[cb.w * 16 + j4]);
        __half2 lo = __hadd2(__hadd2(__hadd2(bits_h2(r0.x), bits_h2(r1.x)),
                                     __hadd2(bits_h2(r2.x), bits_h2(r3.x))),
                             __hadd2(__hadd2(bits_h2(r4.x), bits_h2(r5.x)),
                                     __hadd2(bits_h2(r6.x), bits_h2(r7.x))));
        __half2 hi = __hadd2(__hadd2(__hadd2(bits_h2(r0.y), bits_h2(r1.y)),
                                     __hadd2(bits_h2(r2.y), bits_h2(r3.y))),
                             __hadd2(__hadd2(bits_h2(r4.y), bits_h2(r5.y)),
                                     __hadd2(bits_h2(r6.y), bits_h2(r7.y))));
        float2 flo = __half22float2(lo);
        float2 fhi = __half22float2(hi);
        acc.x += flo.x; acc.y += flo.y; acc.z += fhi.x; acc.w += fhi.y;
    }
    for (; k + 4 <= cnt; k += 4) {
        int4 c4 = __ldg(&c4p[k >> 2]);
        uint2 r0 = __ldg(&xw2[c4.x * 16 + j4]);
        uint2 r1 = __ldg(&xw2[c4.y * 16 + j4]);
        uint2 r2 = __ldg(&xw2[c4.z * 16 + j4]);
        uint2 r3 = __ldg(&xw2[c4.w * 16 + j4]);
        __half2 lo = __hadd2(__hadd2(bits_h2(r0.x), bits_h2(r1.x)),
                             __hadd2(bits_h2(r2.x), bits_h2(r3.x)));
        __half2 hi = __hadd2(__hadd2(bits_h2(r0.y), bits_h2(r1.y)),
                             __hadd2(bits_h2(r2.y), bits_h2(r3.y)));
        float2 flo = __half22float2(lo);
        float2 fhi = __half22float2(hi);
        acc.x += flo.x; acc.y += flo.y; acc.z += fhi.x; acc.w += fhi.y;
    }
    for (; k < cnt; k++) {
        int s = __ldg(&g_col[base + k]);
        uint2 r = __ldg(&xw2[s * 16 + j4]);
        float2 a = __half22float2(bits_h2(r.x));
        float2 b = __half22float2(bits_h2(r.y));
        acc.x += a.x; acc.y += a.y; acc.z += b.x; acc.w += b.y;
    }

    float d = rsqrtf((float)(cnt + 1));
    float4 vb  = ((const float4*)bb)[j4];
    float4 vg  = ((const float4*)gamma)[j4];
    float4 vbt = ((const float4*)beta)[j4];
    float4 vm  = ((const float4*)mean)[j4];
    float4 vv  = ((const float4*)var)[j4];
    float4 o;
    o.x = (acc.x * d + vb.x - vm.x) * (vg.x * rsqrtf(vv.x + EPS_BN)) + vbt.x;
    o.y = (acc.y * d + vb.y - vm.y) * (vg.y * rsqrtf(vv.y + EPS_BN)) + vbt.y;
    o.z = (acc.z * d + vb.z - vm.z) * (vg.z * rsqrtf(vv.z + EPS_BN)) + vbt.z;
    o.w = (acc.w * d + vb.w - vm.w) * (vg.w * rsqrtf(vv.w + EPS_BN)) + vbt.w;
    if (relu) {
        o.x = fmaxf(o.x, 0.f); o.y = fmaxf(o.y, 0.f);
        o.z = fmaxf(o.z, 0.f); o.w = fmaxf(o.w, 0.f);
    }
    ((float4*)g_h)[node * 16 + j4] = o;
}

// -------- fused pooling + classifier + log_softmax: 1 block / graph -----------
__global__ void __launch_bounds__(256) k_poolcls(const int* __restrict__ batch,
                                                 const float* __restrict__ Wc1,
                                                 const float* __restrict__ bc1,
                                                 const float* __restrict__ Wc2,
                                                 const float* __restrict__ bc2,
                                                 float* __restrict__ out) {
    __shared__ int s_se[2];
    __shared__ float ssum[16 * 65];
    __shared__ float smax[16 * 65];
    __shared__ float gv[2 * HID];
    __shared__ float hc[HID];
    __shared__ float lg[C_OUT];
    __shared__ float s_lse;

    int g = blockIdx.x;
    int t = threadIdx.x;

    if (t == 0) {
        int lo = 0, hi = N_NODES;
        while (lo < hi) { int m = (lo + hi) >> 1; if (batch[m] < g) lo = m + 1; else hi = m; }
        s_se[0] = lo;
        lo = 0; hi = N_NODES;
        while (lo < hi) { int m = (lo + hi) >> 1; if (batch[m] < g + 1) lo = m + 1; else hi = m; }
        s_se[1] = lo;
    }
    __syncthreads();
    int start = s_se[0], end = s_se[1];

    int r  = t >> 4;
    int j4 = t & 15;
    const float4* h4 = (const float4*)g_h;
    float4 sum = make_float4(0.f, 0.f, 0.f, 0.f);
    float4 mx  = make_float4(-INFINITY, -INFINITY, -INFINITY, -INFINITY);
    for (int i = start + r; i < end; i += 16) {
        float4 v = h4[i * 16 + j4];
        sum.x += v.x; sum.y += v.y; sum.z += v.z; sum.w += v.w;
        mx.x = fmaxf(mx.x, v.x); mx.y = fmaxf(mx.y, v.y);
        mx.z = fmaxf(mx.z, v.z); mx.w = fmaxf(mx.w, v.w);
    }
    ssum[r * 65 + 4 * j4 + 0] = sum.x; ssum[r * 65 + 4 * j4 + 1] = sum.y;
    ssum[r * 65 + 4 * j4 + 2] = sum.z; ssum[r * 65 + 4 * j4 + 3] = sum.w;
    smax[r * 65 + 4 * j4 + 0] = mx.x;  smax[r * 65 + 4 * j4 + 1] = mx.y;
    smax[r * 65 + 4 * j4 + 2] = mx.z;  smax[r * 65 + 4 * j4 + 3] = mx.w;
    __syncthreads();

    if (t < HID) {
        float s = 0.f, m = -INFINITY;
        #pragma unroll
        for (int q = 0; q < 16; q++) {
            s += ssum[q * 65 + t];
            m = fmaxf(m, smax[q * 65 + t]);
        }
        gv[t]       = s / (float)(end - start);
        gv[HID + t] = m;
    }
    __syncthreads();

    if (t < HID) {
        float s = bc1[t];
        #pragma unroll 16
        for (int k = 0; k < 2 * HID; k++) s += gv[k] * Wc1[k * HID + t];
        hc[t] = fmaxf(s, 0.f);
    }
    __syncthreads();

    if (t < C_OUT) {
        float l = bc2[t];
        #pragma unroll 16
        for (int j = 0; j < HID; j++) l += hc[j] * Wc2[j * C_OUT + t];
        lg[t] = l;
    }
    __syncthreads();

    if (t == 0) {
        float m = -INFINITY;
        #pragma unroll
        for (int c = 0; c < C_OUT; c++) m = fmaxf(m, lg[c]);
        float se = 0.f;
        #pragma unroll
        for (int c = 0; c < C_OUT; c++) se += expf(lg[c] - m);
        s_lse = m + logf(se);
    }
    __syncthreads();
    if (t < C_OUT) out[g * C_OUT + t] = lg[t] - s_lse;
}

extern "C" void kernel_launch(void* const* d_in, const int* in_sizes, int n_in,
                              void* d_out, int out_size) {
    const float* x     = (const float*)d_in[0];
    const int*   ei    = (const int*)  d_in[1];
    const int*   batch = (const int*)  d_in[2];
    // d_in[3] = num_graphs (constant 128, unused)
    const float* W0    = (const float*)d_in[4];
    const float* Ws    = (const float*)d_in[5];
    const float* bs    = (const float*)d_in[6];
    const float* gamma = (const float*)d_in[7];
    const float* beta  = (const float*)d_in[8];
    const float* rmean = (const float*)d_in[9];
    const float* rvar  = (const float*)d_in[10];
    const float* Wc1   = (const float*)d_in[11];
    const float* bc1   = (const float*)d_in[12];
    const float* Wc2   = (const float*)d_in[13];
    const float* bc2   = (const float*)d_in[14];
    float* out = (float*)d_out;

    const int NB_N    = (N_NODES + 255) / 256;
    const int NB_E4   = (N_EDGES / 4 + 255) / 256;
    const int NB_GAT  = N_NODES / 8;           // 12500, 128-thread blocks
    const int NB_GEMM = (N_NODES + 63) / 64;

    // zero-init counters via graph memset nodes
    void* p_ecnt = 0; void* p_tot = 0;
    cudaGetSymbolAddress(&p_ecnt, g_ecnt);
    cudaGetSymbolAddress(&p_tot,  g_tot);
    cudaMemsetAsync(p_ecnt, 0, N_NODES * sizeof(int));
    cudaMemsetAsync(p_tot,  0, sizeof(int));

    // CSR build (fill overlapped with layer-0 linear in one launch)
    k_deg      <<<NB_E4, 256>>>(ei);
    k_base     <<<NB_N, 256>>>();
    k_fill_lin0<<<NB_FILL + NB_L0, 256>>>(ei, x, W0);

    // layer 0 aggregate
    k_gather<<<NB_GAT, 128>>>(bs + 0 * HID, gamma + 0 * HID, beta + 0 * HID,
                              rmean + 0 * HID, rvar + 0 * HID, 1);
    // layer 1
    k_linh  <<<NB_GEMM, 256>>>(Ws + 0 * HID * HID);
    k_gather<<<NB_GAT, 128>>>(bs + 1 * HID, gamma + 1 * HID, beta + 1 * HID,
                              rmean + 1 * HID, rvar + 1 * HID, 1);
    // layer 2 (no relu)
    k_linh  <<<NB_GEMM, 256>>>(Ws + 1 * HID * HID);
    k_gather<<<NB_GAT, 128>>>(bs + 2 * HID, gamma + 2 * HID, beta + 2 * HID,
                              rmean + 2 * HID, rvar + 2 * HID, 0);

    // fused pooling + classifier
    k_poolcls<<<G_NUM, 256>>>(batch, Wc1, bc1, Wc2, bc2, out);
}